// round 10
// baseline (speedup 1.0000x reference)
#include <cuda_runtime.h>
#include <math.h>

// Problem constants (fixed by the reference)
#define N_BAGS   64
#define GRID_W   96
#define NQ       512
#define NMEM     131072
#define DIM      256

#define NBLK     128
#define NTHR     1024
#define NTHREADS (NBLK * NTHR)                 // 131072 == NMEM (1 row/thread)
#define NTASK    (NQ * 8)                      // 4096 (query, neighbor) inserts

#define HBITS    17
#define HSIZE    (1 << HBITS)                  // 131072 slots, load factor 3%
#define HMASK    (HSIZE - 1)
#define MAXM     8                             // max matching queries per row

// Scratch: device globals (no runtime allocation allowed).
// Hash entry: (epoch+1)<<32 | cell<<9 | qi.  Slots whose high word != the
// current launch's tag read as empty -> no zeroing pass, ever. Zero-init BSS
// (tag 0) is stale for every launch since tag = epoch+1 >= 1.
__device__ unsigned long long g_hash[HSIZE];   // 1 MB, L2-resident
__device__ float              g_inv[NQ];       // 5 / ||q_i||
__device__ unsigned           g_epoch;

// ---- software grid barrier (128 CTAs, all co-resident by construction) ----
__device__ unsigned          g_bar_cnt;
__device__ volatile unsigned g_bar_gen;

__device__ __forceinline__ void grid_sync() {
    __syncthreads();
    if (threadIdx.x == 0) {
        __threadfence();
        unsigned gen = g_bar_gen;
        if (atomicAdd(&g_bar_cnt, 1u) == (unsigned)(gridDim.x - 1)) {
            g_bar_cnt = 0;
            __threadfence();
            g_bar_gen = gen + 1;               // release
        } else {
            while (g_bar_gen == gen) { }       // spin (volatile load)
        }
        __threadfence();
    }
    __syncthreads();
}

__device__ __forceinline__ unsigned cell_hash(int cell) {
    return ((unsigned)cell * 2654435761u) >> (32 - HBITS);
}

// ---------------------------------------------------------------------------
// Single fused kernel, ONE grid barrier, inverted matching:
//   P0: insert 4096 (neighbor-cell -> qi) entries into the sparse epoch-
//       tagged hash; compute per-query inverse norms; zero out[].
//   -> barrier ->
//   P1: one memory row per thread: ONE hash load decides (97% home-slot
//       miss). Hitting rows are processed warp-cooperatively.
// ---------------------------------------------------------------------------
__global__ void __launch_bounds__(NTHR, 1)
fused_kernel(const float* __restrict__ q,
             const float* __restrict__ memory,
             const int*   __restrict__ bag_idx,
             const int*   __restrict__ xc,
             const int*   __restrict__ yc,
             const int*   __restrict__ bag_idxs,
             const int*   __restrict__ xs,
             const int*   __restrict__ ys,
             float*       __restrict__ out) {
    const unsigned FULL = 0xFFFFFFFFu;
    int tid  = blockIdx.x * NTHR + threadIdx.x;          // 0 .. 131071
    int lane = threadIdx.x & 31;
    int warp = tid >> 5;

    unsigned epoch = g_epoch;                            // uniform
    unsigned tag   = epoch + 1;                          // >= 1 always

    // ---- Phase 0: inserts + query norms + out zeroing (all tiny) ----
    if (tid < NQ) out[tid] = 0.0f;

    if (warp < NQ) {                                     // per-query 5/||q||
        const float* qr = q + warp * DIM + lane * 8;
        float4 a = *(const float4*)(qr);
        float4 b = *(const float4*)(qr + 4);
        float ss = a.x * a.x + a.y * a.y + a.z * a.z + a.w * a.w
                 + b.x * b.x + b.y * b.y + b.z * b.z + b.w * b.w;
        #pragma unroll
        for (int o = 16; o; o >>= 1) ss += __shfl_xor_sync(FULL, ss, o);
        if (lane == 0) g_inv[warp] = rsqrtf(ss) * 5.0f;
    }

    if (tid < NTASK) {                                   // hash inserts
        int qi = tid >> 3, nb = tid & 7;
        int idx = nb + (nb >= 4 ? 1 : 0);                // skip center
        int dx = idx % 3 - 1, dy = idx / 3 - 1;
        int x = xc[qi] + dx, y = yc[qi] + dy;
        if (x >= 0 && x < GRID_W && y >= 0 && y < GRID_W) {
            int cell = (bag_idx[qi] * GRID_W + y) * GRID_W + x;
            unsigned long long mine =
                ((unsigned long long)tag << 32)
                | ((unsigned long long)(unsigned)cell << 9)
                | (unsigned)qi;
            unsigned h = cell_hash(cell);
            for (;;) {
                unsigned long long cur = g_hash[h];
                bool claimed = false;
                while ((unsigned)(cur >> 32) != tag) {   // stale/empty: claim
                    unsigned long long prev = atomicCAS(&g_hash[h], cur, mine);
                    if (prev == cur) { claimed = true; break; }
                    cur = prev;
                }
                if (claimed) break;
                h = (h + 1) & HMASK;                     // current entry: next
            }
        }
    }
    grid_sync();
    if (tid == 0) g_epoch = epoch + 1;                   // for next launch

    // ---- Phase 1: stream all memory rows, 1 row/thread ----
    int nrow = tid;
    int cell = (bag_idxs[nrow] * GRID_W + ys[nrow]) * GRID_W + xs[nrow];
    unsigned cellkey = (unsigned)cell;

    int m = 0;
    int qm[MAXM];
    {
        unsigned h = cell_hash(cell);
        #pragma unroll 1
        for (int it = 0; it < 64; it++) {
            unsigned long long e = g_hash[h];
            if ((unsigned)(e >> 32) != tag) break;       // stale/empty: done
            unsigned lo = (unsigned)e;
            if ((lo >> 9) == cellkey && m < MAXM) qm[m++] = (int)(lo & 0x1FF);
            h = (h + 1) & HMASK;
        }
    }

    // warp-cooperative processing of all (row, query) hits in this warp
    for (;;) {
        unsigned ball = __ballot_sync(FULL, m > 0);
        if (!ball) break;
        int src  = __ffs(ball) - 1;
        int top  = (m > 0) ? qm[m - 1] : 0;
        int qi_b = __shfl_sync(FULL, top, src);
        int n_b  = __shfl_sync(FULL, nrow, src);

        const float* mr = memory + (size_t)n_b * DIM + lane * 8;
        float4 m0 = *(const float4*)(mr);
        float4 m1 = *(const float4*)(mr + 4);
        const float* qr = q + qi_b * DIM + lane * 8;
        float4 a = *(const float4*)(qr);
        float4 b = *(const float4*)(qr + 4);

        float d = a.x * m0.x + a.y * m0.y + a.z * m0.z + a.w * m0.w
                + b.x * m1.x + b.y * m1.y + b.z * m1.z + b.w * m1.w;
        #pragma unroll
        for (int o = 16; o; o >>= 1) d += __shfl_xor_sync(FULL, d, o);

        if (lane == src) {
            m--;
            atomicAdd(&out[qi_b], expf(d * g_inv[qi_b]));
        }
    }
}

extern "C" void kernel_launch(void* const* d_in, const int* in_sizes, int n_in,
                              void* d_out, int out_size) {
    const float* q        = (const float*)d_in[0];   // [512, 256]
    const float* memory   = (const float*)d_in[1];   // [131072, 256]
    const int*   bag_idx  = (const int*)d_in[2];     // [512]
    const int*   x_coord  = (const int*)d_in[3];     // [512]
    const int*   y_coord  = (const int*)d_in[4];     // [512]
    const int*   bag_idxs = (const int*)d_in[5];     // [131072]
    const int*   x_coords = (const int*)d_in[6];     // [131072]
    const int*   y_coords = (const int*)d_in[7];     // [131072]
    float* out = (float*)d_out;                      // [512]

    fused_kernel<<<NBLK, NTHR>>>(q, memory, bag_idx, x_coord, y_coord,
                                 bag_idxs, x_coords, y_coords, out);
}

// round 12
// speedup vs baseline: 1.0363x; 1.0363x over previous
#include <cuda_runtime.h>
#include <math.h>

// Problem constants (fixed by the reference)
#define N_BAGS   64
#define GRID_W   96
#define NCELLS   (N_BAGS * GRID_W * GRID_W)   // 589824
#define CAP      16        // bucket capacity; Poisson(0.222) => overflow ~impossible
#define NQ       512
#define NMEM     131072
#define DIM      256

#define NBLK     128
#define NTHR     1024                          // 131072 threads == NMEM rows
#define NTASK    (NQ * 8)                      // 4096 tasks == 4096 warps exactly

// Scratch: device globals (no runtime allocation allowed).
// Counter word = (epoch << 8) | cnt. Zero-init == epoch 0 -> launch 0 sees
// every cell as valid-empty. g_epoch bumps once per launch, so stale cells
// (old epoch tag) read as empty without any zeroing pass.
__device__ unsigned g_cnt[NCELLS];
__device__ int      g_cell_items[NCELLS * CAP];
__device__ unsigned g_epoch;

// ---- software grid barrier (128 CTAs, all co-resident by construction) ----
__device__ unsigned          g_bar_cnt;
__device__ volatile unsigned g_bar_gen;

__device__ __forceinline__ void grid_sync() {
    __syncthreads();
    if (threadIdx.x == 0) {
        __threadfence();
        unsigned gen = g_bar_gen;
        if (atomicAdd(&g_bar_cnt, 1u) == (unsigned)(gridDim.x - 1)) {
            g_bar_cnt = 0;
            __threadfence();
            g_bar_gen = gen + 1;               // release
        } else {
            while (g_bar_gen == gen) { }       // spin (volatile load)
        }
        __threadfence();
    }
    __syncthreads();
}

// ---------------------------------------------------------------------------
// Single fused kernel, ONE grid barrier.
//   Pre-barrier (overlapped):
//     - P2 prep: task coords, q-row load, ||q|| reduce  (inputs only)
//     - P1: scatter my one memory row (epoch-tagged slot claim); zero out[]
//   Post-barrier (short chain):
//     - P2: cnt + speculative items in ONE round trip -> rows -> exp -> atomic
// ---------------------------------------------------------------------------
__global__ void __launch_bounds__(NTHR, 1)
fused_kernel(const float* __restrict__ q,
             const float* __restrict__ memory,
             const int*   __restrict__ bag_idx,
             const int*   __restrict__ xc,
             const int*   __restrict__ yc,
             const int*   __restrict__ bag_idxs,
             const int*   __restrict__ xs,
             const int*   __restrict__ ys,
             float*       __restrict__ out) {
    const unsigned FULL = 0xFFFFFFFFu;
    int tid  = blockIdx.x * NTHR + threadIdx.x;          // 0 .. 131071
    int lane = threadIdx.x & 31;

    unsigned epoch = g_epoch;                            // uniform
    unsigned tag   = epoch << 8;

    // ================= PRE-BARRIER (everything overlaps) =================

    // ---- P2 prep: one task per warp, depends only on kernel inputs ----
    int task = tid >> 5;                                 // 0 .. 4095
    int qi   = task >> 3;
    int nb   = task & 7;

    const float* qrow = q + qi * DIM + lane * 8;
    float4 a = *(const float4*)(qrow);
    float4 b = *(const float4*)(qrow + 4);

    int nidx = nb + (nb >= 4 ? 1 : 0);                   // 0..8 skip center
    int dxn = nidx % 3 - 1, dyn = nidx / 3 - 1;
    int xq = xc[qi] + dxn, yq = yc[qi] + dyn;
    bool valid = (xq >= 0) & (xq < GRID_W) & (yq >= 0) & (yq < GRID_W);
    int cell2 = (bag_idx[qi] * GRID_W + yq) * GRID_W + xq;

    float ss = a.x * a.x + a.y * a.y + a.z * a.z + a.w * a.w
             + b.x * b.x + b.y * b.y + b.z * b.z + b.w * b.w;
    #pragma unroll
    for (int o = 16; o; o >>= 1) ss += __shfl_xor_sync(FULL, ss, o);
    float inv = rsqrtf(ss) * 5.0f;                       // 1 / (||q|| * 0.2)

    // ---- P1: scatter my one memory row; zero out[] ----
    if (tid < NQ) out[tid] = 0.0f;
    {
        int n = tid;                                     // exactly NMEM threads
        int cell = (bag_idxs[n] * GRID_W + ys[n]) * GRID_W + xs[n];
        unsigned cur = g_cnt[cell];
        int slot;
        for (;;) {
            if ((cur & 0xFFFFFF00u) == tag) {            // current epoch: add
                unsigned old = atomicAdd(&g_cnt[cell], 1u);
                slot = (int)(old & 0xFFu);
                break;
            }
            unsigned prev = atomicCAS(&g_cnt[cell], cur, tag | 1u);
            if (prev == cur) { slot = 0; break; }        // claimed the reset
            cur = prev;
        }
        if (slot < CAP) g_cell_items[cell * CAP + slot] = n;
    }

    grid_sync();
    if (tid == 0) g_epoch = epoch + 1;                   // for next launch

    // ================= POST-BARRIER (short chain) =================
    if (!valid) return;

    // cnt load and speculative item loads issue in the SAME round trip.
    // Items are garbage-tolerant: array always holds in-range row indices
    // (or zero-init); masked by cnt before any use.
    unsigned word = g_cnt[cell2];
    int item = (lane < CAP) ? g_cell_items[cell2 * CAP + lane] : 0;

    int cnt = ((word & 0xFFFFFF00u) == tag) ? (int)(word & 0xFFu) : 0;
    if (cnt > CAP) cnt = CAP;
    if (cnt == 0) return;

    float s = 0.0f;
    for (int c0 = 0; c0 < cnt; c0 += 4) {
        int k = cnt - c0; if (k > 4) k = 4;
        float d[4];
        #pragma unroll
        for (int j = 0; j < 4; j++) {
            int ci = c0 + j; if (ci >= cnt) ci = cnt - 1;   // dup last (cached)
            int n = __shfl_sync(FULL, item, ci);
            const float* mr = memory + (size_t)n * DIM + lane * 8;
            float4 m0 = *(const float4*)(mr);
            float4 m1 = *(const float4*)(mr + 4);
            d[j] = a.x * m0.x + a.y * m0.y + a.z * m0.z + a.w * m0.w
                 + b.x * m1.x + b.y * m1.y + b.z * m1.z + b.w * m1.w;
        }
        #pragma unroll
        for (int o = 16; o; o >>= 1) {                   // 4 interleaved reductions
            d[0] += __shfl_xor_sync(FULL, d[0], o);
            d[1] += __shfl_xor_sync(FULL, d[1], o);
            d[2] += __shfl_xor_sync(FULL, d[2], o);
            d[3] += __shfl_xor_sync(FULL, d[3], o);
        }
        #pragma unroll
        for (int j = 0; j < 4; j++)
            if (j < k) s += __expf(d[j] * inv);
    }
    if (lane == 0) atomicAdd(&out[qi], s);
}

extern "C" void kernel_launch(void* const* d_in, const int* in_sizes, int n_in,
                              void* d_out, int out_size) {
    const float* q        = (const float*)d_in[0];   // [512, 256]
    const float* memory   = (const float*)d_in[1];   // [131072, 256]
    const int*   bag_idx  = (const int*)d_in[2];     // [512]
    const int*   x_coord  = (const int*)d_in[3];     // [512]
    const int*   y_coord  = (const int*)d_in[4];     // [512]
    const int*   bag_idxs = (const int*)d_in[5];     // [131072]
    const int*   x_coords = (const int*)d_in[6];     // [131072]
    const int*   y_coords = (const int*)d_in[7];     // [131072]
    float* out = (float*)d_out;                      // [512]

    fused_kernel<<<NBLK, NTHR>>>(q, memory, bag_idx, x_coord, y_coord,
                                 bag_idxs, x_coords, y_coords, out);
}